// round 8
// baseline (speedup 1.0000x reference)
#include <cuda_runtime.h>
#include <math.h>
#include <float.h>

#define Bq 4
#define Sq 1024
#define Nk 16384
#define Dm 128
#define KK 16

// ---------------- scratch (device globals; no allocation allowed) ----------------
__device__ float g_cswq[128];
__device__ float g_cswk[128];
__device__ float g_csw2[128];
__device__ float g_consts[4];           // [0]=sum_bq, [1]=sum_bk, [2]=sum_b2
__device__ float g_qsum[Bq * Sq];
__device__ float g_ksum[Bq * Nk];
__device__ float g_attn[Bq * Sq * KK];
__device__ int   g_nidx[Bq * Sq * KK];
__device__ float g_acol[Bq * KK];

// ---------------- prep: column sums of Wq/Wk/W2, bias sums ----------------
__global__ void prep_kernel(const float* __restrict__ Wq, const float* __restrict__ bq,
                            const float* __restrict__ Wk, const float* __restrict__ bk,
                            const float* __restrict__ W2, const float* __restrict__ b2) {
    int i = threadIdx.x;  // 128 threads
    float sq = 0.f, sk = 0.f, s2 = 0.f;
    for (int o = 0; o < 128; o++) {
        sq += Wq[o * 128 + i];
        sk += Wk[o * 128 + i];
        s2 += W2[o * 128 + i];
    }
    g_cswq[i] = sq;
    g_cswk[i] = sk;
    g_csw2[i] = s2;

    float vq = bq[i], vk = bk[i], v2 = b2[i];
    #pragma unroll
    for (int o = 16; o; o >>= 1) {
        vq += __shfl_xor_sync(0xffffffffu, vq, o);
        vk += __shfl_xor_sync(0xffffffffu, vk, o);
        v2 += __shfl_xor_sync(0xffffffffu, v2, o);
    }
    __shared__ float rb[3][4];
    if ((i & 31) == 0) {
        rb[0][i >> 5] = vq; rb[1][i >> 5] = vk; rb[2][i >> 5] = v2;
    }
    __syncthreads();
    if (i == 0) {
        g_consts[0] = rb[0][0] + rb[0][1] + rb[0][2] + rb[0][3];
        g_consts[1] = rb[1][0] + rb[1][1] + rb[1][2] + rb[1][3];
        g_consts[2] = rb[2][0] + rb[2][1] + rb[2][2] + rb[2][3];
    }
}

// ---------------- row sums: feat[row,:] . csw + bias_sum ----------------
__global__ __launch_bounds__(256) void rowsum_kernel(const float* __restrict__ feat,
                                                     int rows, int mode) {
    __shared__ float sc[128];
    int t = threadIdx.x;
    if (t < 128) sc[t] = mode ? g_cswq[t] : g_cswk[t];
    __syncthreads();
    int row = blockIdx.x * 8 + (t >> 5);
    if (row >= rows) return;
    int lane = t & 31;
    float4 v = ((const float4*)feat)[(size_t)row * 32 + lane];
    float4 c = ((const float4*)sc)[lane];
    float d = v.x * c.x + v.y * c.y + v.z * c.z + v.w * c.w;
    #pragma unroll
    for (int o = 16; o; o >>= 1) d += __shfl_xor_sync(0xffffffffu, d, o);
    if (lane == 0) {
        float bs = mode ? g_consts[0] : g_consts[1];
        if (mode) g_qsum[row] = d + bs;
        else      g_ksum[row] = d + bs;
    }
}

// ---------------- KNN + PE-sum + scores + softmax(over k) ----------------
// d2 arithmetic: identical to round-1 (nvcc natural contraction = XLA emission).
// Ordering: ascending d2; bitwise-equal d2 broken by XLA GPU TopK thunk order:
// ascending (idx mod 512, idx div 512)  [512 strided threads, stable merge].
// Key: (d2_bits << 32) | perm(i), perm(i) = ((i&511)<<5)|(i>>9). All d2 >= 0.
__global__ __launch_bounds__(256) void knn_kernel(const float* __restrict__ q_pos,
                                                  const float* __restrict__ k_pos,
                                                  const float* __restrict__ W1,
                                                  const float* __restrict__ b1) {
    constexpr int QPB = 16, TPQ = 16, CH = 2048, NCHK = Nk / CH;
    __shared__ __align__(16) float sbuf[4 * CH];  // xs|ys|zs|kk ; reused as key buffer (32KB)
    __shared__ float sW1[384], sb1[128], sc2[128];
    __shared__ int sIdx[QPB * KK];

    int t  = threadIdx.x;
    int q  = t >> 4;     // query within block
    int tq = t & 15;     // thread within query
    int b  = blockIdx.y;
    int s  = blockIdx.x * QPB + q;

    for (int i = t; i < 384; i += 256) sW1[i] = W1[i];
    if (t < 128) { sb1[t] = b1[t]; sc2[t] = g_csw2[t]; }

    const float* qp = q_pos + ((size_t)(b * Sq + s)) * 3;
    float qx = qp[0], qy = qp[1], qz = qp[2];
    float qq = qx * qx + qy * qy + qz * qz;

    unsigned long long bK[KK];
    #pragma unroll
    for (int j = 0; j < KK; j++) bK[j] = 0xFFFFFFFFFFFFFFFFull;

    float* xs  = sbuf;
    float* ys  = sbuf + CH;
    float* zs  = sbuf + 2 * CH;
    float* kks = sbuf + 3 * CH;

    for (int ch = 0; ch < NCHK; ch++) {
        __syncthreads();
        int base = ch * CH;
        for (int i = t; i < CH; i += 256) {
            const float* kp = k_pos + ((size_t)b * Nk + base + i) * 3;
            float x = kp[0], y = kp[1], z = kp[2];
            xs[i] = x; ys[i] = y; zs[i] = z;
            kks[i] = x * x + y * y + z * z;
        }
        __syncthreads();
        for (int i = tq; i < CH; i += TPQ) {
            float qk = fmaf(qz, zs[i], fmaf(qy, ys[i], qx * xs[i]));
            float d2 = (qq - 2.f * qk) + kks[i];
            int n = base + i;
            unsigned perm = ((unsigned)(n & 511) << 5) | ((unsigned)n >> 9);
            unsigned long long key =
                ((unsigned long long)__float_as_uint(d2) << 32) | (unsigned long long)perm;
            if (key < bK[KK - 1]) {
                bK[KK - 1] = key;
                #pragma unroll
                for (int j = KK - 1; j > 0; j--) {
                    if (bK[j] < bK[j - 1]) {
                        unsigned long long tk = bK[j]; bK[j] = bK[j - 1]; bK[j - 1] = tk;
                    } else break;
                }
            }
        }
    }
    __syncthreads();

    // dump per-thread sorted key lists to SMEM (reuse chunk buffer)
    unsigned long long* sK = (unsigned long long*)sbuf;  // [256][16] = 32KB
    {
        unsigned long long* seg = sK + (size_t)(q * TPQ + tq) * KK;
        #pragma unroll
        for (int j = 0; j < KK; j++) seg[j] = bK[j];
    }
    __syncthreads();

    // leader-merge per query: 16-way merge of sorted key lists -> global top-16
    if (tq == 0) {
        int hp[TPQ];
        #pragma unroll
        for (int u = 0; u < TPQ; u++) hp[u] = 0;
        for (int r = 0; r < KK; r++) {
            unsigned long long bk = 0xFFFFFFFFFFFFFFFFull; int bu = 0;
            for (int u = 0; u < TPQ; u++) {
                int h = hp[u];
                if (h < KK) {
                    unsigned long long kv = sK[(size_t)(q * TPQ + u) * KK + h];
                    if (kv < bk) { bk = kv; bu = u; }
                }
            }
            hp[bu]++;
            unsigned p = (unsigned)(bk & 0x3FFFull);
            sIdx[q * KK + r] = (int)(((p & 31u) << 9) | (p >> 5));
        }
    }
    __syncthreads();

    // per-neighbor PE-sum + score + softmax over the 16 lanes of the half-warp
    int myn = sIdx[q * KK + tq];
    const float* kp = k_pos + ((size_t)b * Nk + myn) * 3;
    float rx = qx - kp[0], ry = qy - kp[1], rz = qz - kp[2];
    float acc = 0.f;
    #pragma unroll 8
    for (int i = 0; i < 128; i++) {
        float h = fmaf(sW1[i * 3], rx, fmaf(sW1[i * 3 + 1], ry, fmaf(sW1[i * 3 + 2], rz, sb1[i])));
        h = fmaxf(h, 0.f);
        acc = fmaf(sc2[i], h, acc);
    }
    float score = g_qsum[b * Sq + s] - g_ksum[b * Nk + myn] + acc + g_consts[2];

    float m = score;
    #pragma unroll
    for (int o = 8; o; o >>= 1) m = fmaxf(m, __shfl_xor_sync(0xffffffffu, m, o, 16));
    float e = expf(score - m);
    float sum = e;
    #pragma unroll
    for (int o = 8; o; o >>= 1) sum += __shfl_xor_sync(0xffffffffu, sum, o, 16);
    float a = e / sum;

    int gi = (b * Sq + s) * KK + tq;
    g_attn[gi] = a;
    g_nidx[gi] = myn;
}

// ---------------- column sums of attn over S, per (b, slot j) ----------------
__global__ __launch_bounds__(256) void colsum_kernel() {
    int b = blockIdx.x >> 4, j = blockIdx.x & 15;
    float s = 0.f;
    for (int ss = threadIdx.x; ss < Sq; ss += 256) s += g_attn[(b * Sq + ss) * KK + j];
    #pragma unroll
    for (int o = 16; o; o >>= 1) s += __shfl_xor_sync(0xffffffffu, s, o);
    __shared__ float r[8];
    if ((threadIdx.x & 31) == 0) r[threadIdx.x >> 5] = s;
    __syncthreads();
    if (threadIdx.x == 0) {
        float tt = 0.f;
        #pragma unroll
        for (int w = 0; w < 8; w++) tt += r[w];
        g_acol[blockIdx.x] = tt;
    }
}

// ---------------- final: normalized gather-aggregate + single GEMM row ----------------
__global__ __launch_bounds__(128) void final_kernel(const float* __restrict__ k_feat,
                                                    const float* __restrict__ Wv,
                                                    const float* __restrict__ bv,
                                                    float* __restrict__ out) {
    constexpr int QPB2 = 32;
    extern __shared__ float sm[];
    float* WvS  = sm;                    // 128 rows x 132 stride (padded, conflict-free f4)
    float* sAgg = sm + 128 * 132;        // 128
    float* sA   = sAgg + 128;            // 16
    int*   sI   = (int*)(sA + 16);       // 16

    int t = threadIdx.x;
    for (int id = t; id < 128 * 128; id += 128) {
        int o = id >> 7, i = id & 127;
        WvS[o * 132 + i] = Wv[id];
    }
    float bvt = bv[t];

    for (int ql = 0; ql < QPB2; ql++) {
        int gq = blockIdx.x * QPB2 + ql;
        int b = gq >> 10;
        __syncthreads();
        if (t < 16) {
            float a = g_attn[gq * KK + t];
            a = a / (g_acol[b * KK + t] + 1e-6f);
            sA[t] = a;
            sI[t] = g_nidx[gq * KK + t];
        }
        __syncthreads();

        float agg = 0.f, asum = 0.f;
        #pragma unroll
        for (int j = 0; j < KK; j++) {
            float a = sA[j];
            asum += a;
            const float* vr = k_feat + ((size_t)(b * Nk) + sI[j]) * 128;
            agg = fmaf(a, vr[t], agg);
        }
        sAgg[t] = agg;
        __syncthreads();

        float a0 = 0.f, a1 = 0.f, a2 = 0.f, a3 = 0.f;
        const float4* wrow = (const float4*)(WvS + t * 132);
        const float4* aggv = (const float4*)sAgg;
        #pragma unroll
        for (int i4 = 0; i4 < 32; i4++) {
            float4 w = wrow[i4];
            float4 g = aggv[i4];
            a0 = fmaf(w.x, g.x, a0);
            a1 = fmaf(w.y, g.y, a1);
            a2 = fmaf(w.z, g.z, a2);
            a3 = fmaf(w.w, g.w, a3);
        }
        out[(size_t)gq * 128 + t] = ((a0 + a1) + (a2 + a3)) + asum * bvt;
    }
}

// ---------------- launch ----------------
extern "C" void kernel_launch(void* const* d_in, const int* in_sizes, int n_in,
                              void* d_out, int out_size) {
    const float* q_feat = (const float*)d_in[0];
    const float* k_feat = (const float*)d_in[1];
    const float* q_pos  = (const float*)d_in[2];
    const float* k_pos  = (const float*)d_in[3];
    const float* Wq     = (const float*)d_in[4];
    const float* bq     = (const float*)d_in[5];
    const float* Wk     = (const float*)d_in[6];
    const float* bk     = (const float*)d_in[7];
    const float* Wv     = (const float*)d_in[8];
    const float* bv     = (const float*)d_in[9];
    const float* W1     = (const float*)d_in[10];
    const float* b1     = (const float*)d_in[11];
    const float* W2     = (const float*)d_in[12];
    const float* b2     = (const float*)d_in[13];
    float* out = (float*)d_out;

    prep_kernel<<<1, 128>>>(Wq, bq, Wk, bk, W2, b2);
    rowsum_kernel<<<(Bq * Nk) / 8, 256>>>(k_feat, Bq * Nk, 0);
    rowsum_kernel<<<(Bq * Sq) / 8, 256>>>(q_feat, Bq * Sq, 1);
    knn_kernel<<<dim3(Sq / 16, Bq), 256>>>(q_pos, k_pos, W1, b1);
    colsum_kernel<<<Bq * KK, 256>>>();

    int smemF = (128 * 132 + 128 + 16 + 16) * (int)sizeof(float);
    cudaFuncSetAttribute(final_kernel, cudaFuncAttributeMaxDynamicSharedMemorySize, smemF);
    final_kernel<<<(Bq * Sq) / 32, 128, smemF>>>(k_feat, Wv, bv, out);
}